// round 6
// baseline (speedup 1.0000x reference)
#include <cuda_runtime.h>

#define Bsz 4096
#define Lsz 512
#define Msz 17
#define Hsz 17
#define Tch 4
#define NCHUNK (Lsz / Tch)        // 128
#define WPB 10                    // warps per block
#define NTHREADS (WPB * 32)       // 320
#define NBLOCKS 148
#define NWARPS (NBLOCKS * WPB)    // 1480

typedef unsigned long long u64;

__device__ __forceinline__ u64 pk2(float a, float b) {
    u64 r; asm("mov.b64 %0, {%1, %2};" : "=l"(r) : "f"(a), "f"(b)); return r;
}
__device__ __forceinline__ void upk2(u64 v, float &a, float &b) {
    asm("mov.b64 {%0, %1}, %2;" : "=f"(a), "=f"(b) : "l"(v));
}
__device__ __forceinline__ void ffma2(u64 &d, u64 a, u64 b) {
    asm("fma.rn.f32x2 %0, %1, %2, %0;" : "+l"(d) : "l"(a), "l"(b));
}
__device__ __forceinline__ float sigm(float z) {
    return __fdividef(1.0f, 1.0f + __expf(-z));
}
__device__ __forceinline__ float tanh_(float z) {
    return __fdividef(2.0f, 1.0f + __expf(-2.0f * z)) - 1.0f;
}

__global__ __launch_bounds__(NTHREADS, 1) void lstm_warp_kernel(
    const float* __restrict__ x,
    const float* __restrict__ Wih,
    const float* __restrict__ Whh,
    const float* __restrict__ bih,
    const float* __restrict__ bhh,
    float* __restrict__ out)
{
    // warp-private staging; all inner-loop reads are LDS broadcasts (1 wf)
    __shared__ float sxs[WPB][Tch][18];   // x chunk, plain, padded (slot 17 = 0)
    __shared__ float shh[WPB][20];        // h state, plain, padded (slot 17 = 0)
    __shared__ float shb[WPB][68];        // h output staging (4 steps)

    const int lane = threadIdx.x & 31;
    const int w    = threadIdx.x >> 5;
    const int jj   = (lane < Hsz) ? lane : (Hsz - 1);   // clamp idle lanes

    // ---- pack weights per gate as natural pairs (pad pair 8 = (w16, 0)) ----
    u64 wip[4][9], whp[4][9], biasp[4];
#pragma unroll
    for (int g = 0; g < 4; g++) {
        const float* wi = Wih + (g * Hsz + jj) * Msz;
        const float* wh = Whh + (g * Hsz + jj) * Hsz;
#pragma unroll
        for (int p = 0; p < 8; p++) {
            wip[g][p] = pk2(wi[2 * p], wi[2 * p + 1]);
            whp[g][p] = pk2(wh[2 * p], wh[2 * p + 1]);
        }
        wip[g][8] = pk2(wi[16], 0.0f);
        whp[g][8] = pk2(wh[16], 0.0f);
        biasp[g]  = pk2(bih[g * Hsz + jj] + bhh[g * Hsz + jj], 0.0f);
    }

    // zero pads once
    if (lane < Tch) sxs[w][lane][17] = 0.0f;
    if (lane < 20 && lane >= Hsz) shh[w][lane] = 0.0f;

    const long OUT_ELEMS = (long)Bsz * Lsz * Hsz;
    const long H_OFF = OUT_ELEMS;
    const long C_OFF = OUT_ELEMS + (long)Bsz * Hsz;
    const long X_OFF = OUT_ELEMS + 2L * (long)Bsz * Hsz;

    const int wg = blockIdx.x * WPB + w;   // global warp id

#pragma unroll 1
    for (int r = 0; r < 3; r++) {
        const int rowb = wg + r * NWARPS;
        if (rowb >= Bsz) break;

        const float4* xrow4 = (const float4*)(x + (long)rowb * Lsz * Msz);
        float4*       xo4   = (float4*)(out + X_OFF + (long)rowb * Lsz * Msz);
        float*        obase = out + (long)rowb * Lsz * Hsz;

        // reset h state
        if (lane < Hsz) shh[w][lane] = 0.0f;
        float c = 0.0f, hn = 0.0f;

        // prefetch chunk 0 (17 float4 = 68 floats)
        float4 v;
        if (lane < Msz) v = xrow4[lane];
        __syncwarp();

#pragma unroll 1
        for (int ch = 0; ch < NCHUNK; ch++) {
            // ---- stage x chunk + mirror to passthrough ----
            if (lane < Msz) {
                xo4[ch * Msz + lane] = v;
                float f[4] = {v.x, v.y, v.z, v.w};
                const int fb = 4 * lane;
#pragma unroll
                for (int i = 0; i < 4; i++) {
                    int fi = fb + i;
                    int t = fi / Msz, k = fi - Msz * t;
                    sxs[w][t][k] = f[i];
                }
                // prefetch next chunk
                if (ch + 1 < NCHUNK) v = xrow4[(ch + 1) * Msz + lane];
            }
            __syncwarp();

#pragma unroll
            for (int tl = 0; tl < Tch; tl++) {
                u64 acc0 = biasp[0], acc1 = biasp[1], acc2 = biasp[2], acc3 = biasp[3];

                const u64* xp = (const u64*)sxs[w][tl];   // 72B-aligned rows
                const u64* hp = (const u64*)shh[w];
#pragma unroll
                for (int p = 0; p < 9; p++) {
                    const u64 xv = xp[p];                  // LDS.64 broadcast
                    ffma2(acc0, wip[0][p], xv);
                    ffma2(acc1, wip[1][p], xv);
                    ffma2(acc2, wip[2][p], xv);
                    ffma2(acc3, wip[3][p], xv);
                }
#pragma unroll
                for (int p = 0; p < 9; p++) {
                    const u64 hv = hp[p];                  // LDS.64 broadcast
                    ffma2(acc0, whp[0][p], hv);
                    ffma2(acc1, whp[1][p], hv);
                    ffma2(acc2, whp[2][p], hv);
                    ffma2(acc3, whp[3][p], hv);
                }

                float l0, h0, l1, h1, l2, h2, l3, h3;
                upk2(acc0, l0, h0); upk2(acc1, l1, h1);
                upk2(acc2, l2, h2); upk2(acc3, l3, h3);
                const float zi = l0 + h0, zf = l1 + h1, zg = l2 + h2, zo = l3 + h3;

                const float ig = sigm(zi);
                const float fg = sigm(zf);
                const float gg = tanh_(zg);
                const float og = sigm(zo);
                c  = fg * c + ig * gg;
                hn = og * tanh_(c);

                __syncwarp();        // all lanes done reading shh for this step
                if (lane < Hsz) {
                    shh[w][lane] = hn;
                    shb[w][tl * Hsz + lane] = hn;
                }
                __syncwarp();        // writes visible before next step's reads
            }

            // ---- flush 4 steps of h (coalesced float4) ----
            if (lane < Msz) {
                const float4 hv4 = ((const float4*)shb[w])[lane];
                ((float4*)(obase + ch * (Tch * Hsz)))[lane] = hv4;
            }
        }

        if (lane < Hsz) {
            out[H_OFF + (long)rowb * Hsz + lane] = hn;
            out[C_OFF + (long)rowb * Hsz + lane] = c;
        }
        __syncwarp();
    }
}

extern "C" void kernel_launch(void* const* d_in, const int* in_sizes, int n_in,
                              void* d_out, int out_size) {
    const float* x   = (const float*)d_in[0];
    const float* Wih = (const float*)d_in[1];
    const float* Whh = (const float*)d_in[2];
    const float* bih = (const float*)d_in[3];
    const float* bhh = (const float*)d_in[4];
    float* out = (float*)d_out;
    (void)in_sizes; (void)n_in; (void)out_size;

    lstm_warp_kernel<<<NBLOCKS, NTHREADS>>>(x, Wih, Whh, bih, bhh, out);
}

// round 7
// speedup vs baseline: 1.6381x; 1.6381x over previous
#include <cuda_runtime.h>

#define Bsz 4096
#define Lsz 512
#define Msz 17
#define Hsz 17
#define Tch 4
#define NCHUNK (Lsz / Tch)          // 128
#define BLOCK_B 28
#define NTHREADS (BLOCK_B * Hsz)    // 476
#define NBLOCKS ((Bsz + BLOCK_B - 1) / BLOCK_B)  // 147

typedef unsigned long long u64;

__device__ __forceinline__ u64 pk2(float a, float b) {
    u64 r; asm("mov.b64 %0, {%1, %2};" : "=l"(r) : "f"(a), "f"(b)); return r;
}
__device__ __forceinline__ void upk2(u64 v, float &a, float &b) {
    asm("mov.b64 {%0, %1}, %2;" : "=f"(a), "=f"(b) : "l"(v));
}
__device__ __forceinline__ void ffma2(u64 &d, u64 a, u64 b) {
    asm("fma.rn.f32x2 %0, %1, %2, %0;" : "+l"(d) : "l"(a), "l"(b));
}
__device__ __forceinline__ float sigm(float z) {
    return __fdividef(1.0f, 1.0f + __expf(-z));
}
__device__ __forceinline__ float tanh_(float z) {
    return __fdividef(2.0f, 1.0f + __expf(-2.0f * z)) - 1.0f;
}

__global__ __launch_bounds__(NTHREADS, 1) void lstm_fused_kernel(
    const float* __restrict__ x,
    const float* __restrict__ Wih,
    const float* __restrict__ Whh,
    const float* __restrict__ bih,
    const float* __restrict__ bhh,
    float* __restrict__ out)
{
    __shared__ u64 wih_if_s[Msz * Hsz];            // W_ih gate-pairs (i,f)
    __shared__ u64 wih_go_s[Msz * Hsz];            // W_ih gate-pairs (g,o)
    __shared__ u64 sx[BLOCK_B][Tch * Msz];         // x chunk, dup f32x2, idx k*4+t
    __shared__ float shp[2][BLOCK_B][20];          // h state, PLAIN floats, dbl-buffered
    __shared__ float hbuf[BLOCK_B][2 * Tch * Hsz]; // 8-step h output ring

    const int tid = threadIdx.x;
    const int j = tid % Hsz;
    const int y = tid / Hsz;
    const int b = blockIdx.x * BLOCK_B + y;
    const bool act = (b < Bsz);
    const int bb = act ? b : (Bsz - 1);

    // ---- W_ih into smem, gate-pair packed per (k,j) ----
    if (tid < Msz * Hsz) {
        int k = tid / Hsz, jj = tid % Hsz;
        wih_if_s[tid] = pk2(Wih[jj * Msz + k],             Wih[(Hsz + jj) * Msz + k]);
        wih_go_s[tid] = pk2(Wih[(2 * Hsz + jj) * Msz + k], Wih[(3 * Hsz + jj) * Msz + k]);
    }

    // ---- W_hh in registers, NATURAL pairs per gate: (w[2p], w[2p+1]) ----
    u64 wh0[9], wh1[9], wh2[9], wh3[9];
    {
        const float* w0 = Whh + (0 * Hsz + j) * Hsz;
        const float* w1 = Whh + (1 * Hsz + j) * Hsz;
        const float* w2 = Whh + (2 * Hsz + j) * Hsz;
        const float* w3 = Whh + (3 * Hsz + j) * Hsz;
#pragma unroll
        for (int p = 0; p < 8; p++) {
            wh0[p] = pk2(w0[2 * p], w0[2 * p + 1]);
            wh1[p] = pk2(w1[2 * p], w1[2 * p + 1]);
            wh2[p] = pk2(w2[2 * p], w2[2 * p + 1]);
            wh3[p] = pk2(w3[2 * p], w3[2 * p + 1]);
        }
        wh0[8] = pk2(w0[16], 0.0f);
        wh1[8] = pk2(w1[16], 0.0f);
        wh2[8] = pk2(w2[16], 0.0f);
        wh3[8] = pk2(w3[16], 0.0f);
    }
    const u64 b_if = pk2(bih[j] + bhh[j],                     bih[Hsz + j] + bhh[Hsz + j]);
    const u64 b_go = pk2(bih[2 * Hsz + j] + bhh[2 * Hsz + j], bih[3 * Hsz + j] + bhh[3 * Hsz + j]);

    const long OUT_ELEMS = (long)Bsz * Lsz * Hsz;
    const long H_OFF = OUT_ELEMS;
    const long C_OFF = OUT_ELEMS + (long)Bsz * Hsz;
    const long X_OFF = OUT_ELEMS + 2L * (long)Bsz * Hsz;

    const float4* xrow4 = (const float4*)(x + (long)bb * Lsz * Msz);
    float4*       xo4   = (float4*)(out + X_OFF + (long)bb * Lsz * Msz);
    float*        obase = out + (long)bb * Lsz * Hsz;

    // init h state + pads (pad slot 17 must be finite: wh*[8].hi==0 kills it)
    shp[0][y][j] = 0.0f;
    shp[1][y][j] = 0.0f;
    if (j == 0) { shp[0][y][17] = 0.0f; shp[1][y][17] = 0.0f; }
    float c = 0.0f, hn = 0.0f;

    // prefetch first x chunk
    float4 v = xrow4[j];

    for (int ch = 0; ch < NCHUNK; ch++) {
        const int t0 = ch * Tch;

        // ---- stage chunk (held in v): mirror to x passthrough + dup into sx ----
        if (act) xo4[ch * Msz + j] = v;
        {
            float f[4] = {v.x, v.y, v.z, v.w};
            const int fbase = 4 * j;
#pragma unroll
            for (int i = 0; i < 4; i++) {
                int fi = fbase + i;
                int t = fi / Msz, k = fi - Msz * t;
                sx[y][k * Tch + t] = pk2(f[i], f[i]);
            }
        }
        if (ch + 1 < NCHUNK) v = xrow4[(ch + 1) * Msz + j];
        __syncthreads();

        // ---- 4-step x-projection burst (gate-pair packed, amortized weights) ----
        u64 a_if[Tch], a_go[Tch];
#pragma unroll
        for (int t = 0; t < Tch; t++) { a_if[t] = b_if; a_go[t] = b_go; }
#pragma unroll
        for (int k = 0; k < Msz; k++) {
            const u64 wf = wih_if_s[k * Hsz + j];
            const u64 wg = wih_go_s[k * Hsz + j];
            const ulonglong2 x01 = ((const ulonglong2*)&sx[y][k * Tch])[0];
            const ulonglong2 x23 = ((const ulonglong2*)&sx[y][k * Tch])[1];
            ffma2(a_if[0], wf, x01.x); ffma2(a_go[0], wg, x01.x);
            ffma2(a_if[1], wf, x01.y); ffma2(a_go[1], wg, x01.y);
            ffma2(a_if[2], wf, x23.x); ffma2(a_go[2], wg, x23.x);
            ffma2(a_if[3], wf, x23.y); ffma2(a_go[3], wg, x23.y);
        }

        // ---- 4 recurrence steps: plain-h broadcast reads, per-gate accums ----
#pragma unroll
        for (int tl = 0; tl < Tch; tl++) {
            const int t = t0 + tl;
            const int cur = t & 1, nxt = cur ^ 1;

            u64 hc0 = 0ULL, hc1 = 0ULL, hc2 = 0ULL, hc3 = 0ULL;
            const u64* hp = (const u64*)shp[cur][y];
#pragma unroll
            for (int p = 0; p < 9; p++) {
                const u64 hv = hp[p];          // LDS.64 broadcast (plain pair)
                ffma2(hc0, wh0[p], hv);
                ffma2(hc1, wh1[p], hv);
                ffma2(hc2, wh2[p], hv);
                ffma2(hc3, wh3[p], hv);
            }

            float xi, xf, xg, xo_;
            upk2(a_if[tl], xi, xf);
            upk2(a_go[tl], xg, xo_);
            float l, h;
            upk2(hc0, l, h); const float zi = xi + (l + h);
            upk2(hc1, l, h); const float zf = xf + (l + h);
            upk2(hc2, l, h); const float zg = xg + (l + h);
            upk2(hc3, l, h); const float zo = xo_ + (l + h);

            const float ig = sigm(zi);
            const float fg = sigm(zf);
            const float gg = tanh_(zg);
            const float og = sigm(zo);
            c  = fg * c + ig * gg;
            hn = og * tanh_(c);

            hbuf[y][(t & 7) * Hsz + j] = hn;
            shp[nxt][y][j] = hn;               // plain STS.32
            __syncthreads();
        }

        // ---- flush 4 steps of h (coalesced float4) ----
        if (act) {
            const int half = ch & 1;
            const float4 hv4 = ((const float4*)&hbuf[y][half * (Tch * Hsz)])[j];
            ((float4*)(obase + t0 * Hsz))[j] = hv4;
        }
    }

    if (act) {
        out[H_OFF + (long)b * Hsz + j] = hn;
        out[C_OFF + (long)b * Hsz + j] = c;
    }
}

extern "C" void kernel_launch(void* const* d_in, const int* in_sizes, int n_in,
                              void* d_out, int out_size) {
    const float* x   = (const float*)d_in[0];
    const float* Wih = (const float*)d_in[1];
    const float* Whh = (const float*)d_in[2];
    const float* bih = (const float*)d_in[3];
    const float* bhh = (const float*)d_in[4];
    float* out = (float*)d_out;
    (void)in_sizes; (void)n_in; (void)out_size;

    lstm_fused_kernel<<<NBLOCKS, NTHREADS>>>(x, Wih, Whh, bih, bhh, out);
}